// round 13
// baseline (speedup 1.0000x reference)
#include <cuda_runtime.h>
#include <cuda_bf16.h>
#include <math.h>
#include <stdint.h>

// Problem constants
#define TOKENS 8192      // B*N = 8*1024
#define BATCH  8
#define SEQ    1024
#define C_DIM  768
#define KV_DIM 1536
#define HID    3072
#define HEADS  12
#define DH     64

// ---------------------------------------------------------------------------
// Scratch (device globals; no runtime allocation)
// ---------------------------------------------------------------------------
__device__ __nv_bfloat16 g_xn_h [TOKENS * C_DIM];
__device__ __nv_bfloat16 g_xn_l [TOKENS * C_DIM];
__device__ float         g_kv   [TOKENS * KV_DIM];
__device__ __nv_bfloat16 g_att_h[TOKENS * C_DIM];
__device__ __nv_bfloat16 g_att_l[TOKENS * C_DIM];
__device__ float         g_x2   [TOKENS * C_DIM];
__device__ __nv_bfloat16 g_h_h  [TOKENS * C_DIM];
__device__ __nv_bfloat16 g_h_l  [TOKENS * C_DIM];
__device__ __nv_bfloat16 g_hh_h [TOKENS * HID];
__device__ __nv_bfloat16 g_hh_l [TOKENS * HID];

// Transposed + bf16-split weights: [N, K] row-major (i.e. W^T)
__device__ __nv_bfloat16 g_wkv_h [KV_DIM * C_DIM];
__device__ __nv_bfloat16 g_wkv_l [KV_DIM * C_DIM];
__device__ __nv_bfloat16 g_wout_h[C_DIM * C_DIM];
__device__ __nv_bfloat16 g_wout_l[C_DIM * C_DIM];
__device__ __nv_bfloat16 g_w1_h  [HID * C_DIM];
__device__ __nv_bfloat16 g_w1_l  [HID * C_DIM];
__device__ __nv_bfloat16 g_w2_h  [C_DIM * HID];
__device__ __nv_bfloat16 g_w2_l  [C_DIM * HID];

// ---------------------------------------------------------------------------
// Helpers
// ---------------------------------------------------------------------------
__device__ __forceinline__ void bsplit(float v, __nv_bfloat16& h, __nv_bfloat16& l) {
    h = __float2bfloat16(v);
    l = __float2bfloat16(v - __bfloat162float(h));
}

// bf16 m16n8k16 MMA (row.col), fp32 accumulate — supported on plain sm_103
__device__ __forceinline__ void mma_bf16(float* c, const uint32_t* a,
                                         uint32_t b0, uint32_t b1) {
    asm volatile(
        "mma.sync.aligned.m16n8k16.row.col.f32.bf16.bf16.f32 "
        "{%0,%1,%2,%3}, {%4,%5,%6,%7}, {%8,%9}, {%0,%1,%2,%3};"
        : "+f"(c[0]), "+f"(c[1]), "+f"(c[2]), "+f"(c[3])
        : "r"(a[0]), "r"(a[1]), "r"(a[2]), "r"(a[3]), "r"(b0), "r"(b1));
}

#define CP_ASYNC16(smem_u32, gptr) \
    asm volatile("cp.async.cg.shared.global [%0], [%1], 16;" \
        :: "r"(smem_u32), "l"(gptr) : "memory")
#define CP_COMMIT() asm volatile("cp.async.commit_group;" ::: "memory")
#define CP_WAIT1()  asm volatile("cp.async.wait_group 1;" ::: "memory")
#define CP_WAIT0()  asm volatile("cp.async.wait_group 0;" ::: "memory")

// ---------------------------------------------------------------------------
// Weight transpose + bf16 split: w[K,N] fp32 -> th/tl[N,K] bf16
// ---------------------------------------------------------------------------
__global__ void __launch_bounds__(256) wsplit_t(
    const float* __restrict__ w, __nv_bfloat16* __restrict__ th,
    __nv_bfloat16* __restrict__ tl, int K, int N)
{
    __shared__ float tile[32][33];
    const int n0 = blockIdx.x * 32, k0 = blockIdx.y * 32;
    const int tx = threadIdx.x, ty = threadIdx.y;
    #pragma unroll
    for (int i = ty; i < 32; i += 8)
        tile[i][tx] = w[(size_t)(k0 + i) * N + n0 + tx];
    __syncthreads();
    #pragma unroll
    for (int i = ty; i < 32; i += 8) {
        float v = tile[tx][i];                 // = w[k0+tx][n0+i]
        __nv_bfloat16 h, l; bsplit(v, h, l);
        size_t o = (size_t)(n0 + i) * K + k0 + tx;
        th[o] = h; tl[o] = l;
    }
}

// ---------------------------------------------------------------------------
// LayerNorm -> bf16 hi/lo outputs
// ---------------------------------------------------------------------------
__global__ void __launch_bounds__(256) ln_kernel(
    const float* __restrict__ x, const float* __restrict__ g,
    const float* __restrict__ b,
    __nv_bfloat16* __restrict__ hi, __nv_bfloat16* __restrict__ lo)
{
    __shared__ float sh[9];
    const int row = blockIdx.x;
    const int t = threadIdx.x;
    const float* xr = x + (size_t)row * C_DIM;

    float v0 = xr[t], v1 = xr[t + 256], v2 = xr[t + 512];

    float s = v0 + v1 + v2;
    #pragma unroll
    for (int o = 16; o; o >>= 1) s += __shfl_xor_sync(0xffffffffu, s, o);
    if ((t & 31) == 0) sh[t >> 5] = s;
    __syncthreads();
    if (t == 0) {
        float a = 0.f;
        #pragma unroll
        for (int i = 0; i < 8; i++) a += sh[i];
        sh[8] = a * (1.0f / C_DIM);
    }
    __syncthreads();
    const float mu = sh[8];

    float d0 = v0 - mu, d1 = v1 - mu, d2 = v2 - mu;
    float q = d0 * d0 + d1 * d1 + d2 * d2;
    __syncthreads();
    #pragma unroll
    for (int o = 16; o; o >>= 1) q += __shfl_xor_sync(0xffffffffu, q, o);
    if ((t & 31) == 0) sh[t >> 5] = q;
    __syncthreads();
    if (t == 0) {
        float a = 0.f;
        #pragma unroll
        for (int i = 0; i < 8; i++) a += sh[i];
        sh[8] = rsqrtf(a * (1.0f / C_DIM) + 1e-5f);
    }
    __syncthreads();
    const float rs = sh[8];

    const size_t rb = (size_t)row * C_DIM;
    float vals[3] = { d0 * rs * g[t] + b[t],
                      d1 * rs * g[t + 256] + b[t + 256],
                      d2 * rs * g[t + 512] + b[t + 512] };
    #pragma unroll
    for (int i = 0; i < 3; i++) {
        __nv_bfloat16 h, l; bsplit(vals[i], h, l);
        hi[rb + t + i * 256] = h;
        lo[rb + t + i * 256] = l;
    }
}

// ---------------------------------------------------------------------------
// bf16x3 tensor-core GEMM: C[M,N] = A @ Bt^T (+bias)(+resid | GELU)
// A: bf16 hi/lo [M,K] row-major; Bt: bf16 hi/lo [N,K] row-major.
// mma.m16n8k16 bf16, fp32 accum. Block tile 128x128, BK=32, 256 thr, 8 warps
// (2x4, warp tile 64x32). cp.async double-buffered smem, stride-40 layout
// (bank = (20g+ti)%32 — conflict-free fragment reads).
// ---------------------------------------------------------------------------
enum { EPI_NONE = 0, EPI_BIAS_RES = 1, EPI_BIAS_GELU = 2 };
enum { OUT_F32 = 0, OUT_BF16 = 1 };

#define BK 32
#define ST 40                       // smem row stride in bf16 elems
#define ARR_ELEMS (128 * ST)        // 5120 bf16 = 10240 B per array
#define STAGE_ELEMS (4 * ARR_ELEMS) // Ah, Al, Bh, Bl
#define TG_SMEM (2 * STAGE_ELEMS * 2)  // bytes = 81920

template <int EPI, int OUTM>
__global__ void __launch_bounds__(256) tgemm_bf3(
    int M, int N, int K,
    const __nv_bfloat16* __restrict__ Ahi, const __nv_bfloat16* __restrict__ Alo,
    const __nv_bfloat16* __restrict__ Bth, const __nv_bfloat16* __restrict__ Btl,
    const float* __restrict__ bias, const float* __restrict__ resid,
    float* __restrict__ C,
    __nv_bfloat16* __restrict__ Chi, __nv_bfloat16* __restrict__ Clo)
{
    extern __shared__ __nv_bfloat16 smem[];
    const uint32_t smb = (uint32_t)__cvta_generic_to_shared(smem);

    const int t    = threadIdx.x;
    const int lane = t & 31;
    const int warp = t >> 5;
    const int wm   = (warp >> 2) * 64;   // 0 or 64
    const int wn   = (warp & 3) * 32;    // 0,32,64,96
    const int g    = lane >> 2;          // 0..7
    const int ti   = lane & 3;           // 0..3

    const __nv_bfloat16* Ab_h = Ahi + (size_t)blockIdx.y * 128 * K;
    const __nv_bfloat16* Ab_l = Alo + (size_t)blockIdx.y * 128 * K;
    const __nv_bfloat16* Bb_h = Bth + (size_t)blockIdx.x * 128 * K;
    const __nv_bfloat16* Bb_l = Btl + (size_t)blockIdx.x * 128 * K;
    const __nv_bfloat16* srcs[4] = { Ab_h, Ab_l, Bb_h, Bb_l };

    // loader: per array 128 rows x 32 cols bf16 = 512 uint4; 2 per thread
    const int r0l = (t) >> 2,        q0l = (t) & 3;
    const int r1l = (t + 256) >> 2,  q1l = (t + 256) & 3;

    auto issue = [&](int c) {
        const int s = c & 1;
        const uint32_t sb = smb + s * (STAGE_ELEMS * 2);
        #pragma unroll
        for (int arr = 0; arr < 4; ++arr) {
            const __nv_bfloat16* src = srcs[arr] + c * BK;
            const uint32_t db = sb + arr * (ARR_ELEMS * 2);
            CP_ASYNC16(db + (uint32_t)(r0l * (ST * 2) + q0l * 16),
                       src + (size_t)r0l * K + q0l * 8);
            CP_ASYNC16(db + (uint32_t)(r1l * (ST * 2) + q1l * 16),
                       src + (size_t)r1l * K + q1l * 8);
        }
        CP_COMMIT();
    };

    float acc[4][4][4];
    #pragma unroll
    for (int i = 0; i < 4; i++)
        #pragma unroll
        for (int j = 0; j < 4; j++)
            #pragma unroll
            for (int k = 0; k < 4; k++) acc[i][j][k] = 0.f;

    const int nStages = K / BK;
    issue(0);
    if (nStages > 1) issue(1);

    for (int c = 0; c < nStages; ++c) {
        if (c + 1 < nStages) { CP_WAIT1(); } else { CP_WAIT0(); }
        __syncthreads();

        const int s = c & 1;
        const __nv_bfloat16* sAh = smem + s * STAGE_ELEMS;
        const __nv_bfloat16* sAl = sAh + ARR_ELEMS;
        const __nv_bfloat16* sBh = sAl + ARR_ELEMS;
        const __nv_bfloat16* sBl = sBh + ARR_ELEMS;

        #pragma unroll
        for (int ks = 0; ks < BK; ks += 16) {
            uint32_t ah[4][4], al[4][4];
            #pragma unroll
            for (int ib = 0; ib < 4; ++ib) {
                const int rb = (wm + ib * 16 + g) * ST + ks + 2 * ti;
                ah[ib][0] = *reinterpret_cast<const uint32_t*>(sAh + rb);
                ah[ib][1] = *reinterpret_cast<const uint32_t*>(sAh + rb + 8 * ST);
                ah[ib][2] = *reinterpret_cast<const uint32_t*>(sAh + rb + 8);
                ah[ib][3] = *reinterpret_cast<const uint32_t*>(sAh + rb + 8 * ST + 8);
                al[ib][0] = *reinterpret_cast<const uint32_t*>(sAl + rb);
                al[ib][1] = *reinterpret_cast<const uint32_t*>(sAl + rb + 8 * ST);
                al[ib][2] = *reinterpret_cast<const uint32_t*>(sAl + rb + 8);
                al[ib][3] = *reinterpret_cast<const uint32_t*>(sAl + rb + 8 * ST + 8);
            }
            #pragma unroll
            for (int jb = 0; jb < 4; ++jb) {
                const int nb = (wn + jb * 8 + g) * ST + ks + 2 * ti;
                const uint32_t bh0 = *reinterpret_cast<const uint32_t*>(sBh + nb);
                const uint32_t bh1 = *reinterpret_cast<const uint32_t*>(sBh + nb + 8);
                const uint32_t bl0 = *reinterpret_cast<const uint32_t*>(sBl + nb);
                const uint32_t bl1 = *reinterpret_cast<const uint32_t*>(sBl + nb + 8);
                #pragma unroll
                for (int ib = 0; ib < 4; ++ib) {
                    mma_bf16(acc[ib][jb], ah[ib], bh0, bh1);   // hi*hi
                    mma_bf16(acc[ib][jb], ah[ib], bl0, bl1);   // hi*lo
                    mma_bf16(acc[ib][jb], al[ib], bh0, bh1);   // lo*hi
                }
            }
        }
        __syncthreads();
        if (c + 2 < nStages) issue(c + 2);
    }

    // Epilogue: c0,c1 at (g, 2ti/(+1)); c2,c3 at (g+8, ...)
    const int row0 = blockIdx.y * 128 + wm;
    const int col0 = blockIdx.x * 128 + wn;
    #pragma unroll
    for (int ib = 0; ib < 4; ++ib) {
        #pragma unroll
        for (int jb = 0; jb < 4; ++jb) {
            const int cc = col0 + jb * 8 + 2 * ti;
            #pragma unroll
            for (int half = 0; half < 2; half++) {
                const int r = row0 + ib * 16 + g + half * 8;
                float e0 = acc[ib][jb][half * 2 + 0];
                float e1 = acc[ib][jb][half * 2 + 1];
                const size_t off = (size_t)r * N + cc;
                if (EPI != EPI_NONE) {
                    e0 += bias[cc];
                    e1 += bias[cc + 1];
                }
                if (EPI == EPI_BIAS_RES) {
                    float2 rr = *reinterpret_cast<const float2*>(resid + off);
                    e0 += rr.x;
                    e1 += rr.y;
                }
                if (EPI == EPI_BIAS_GELU) {
                    e0 = 0.5f * e0 * (1.0f + erff(e0 * 0.70710678118654752f));
                    e1 = 0.5f * e1 * (1.0f + erff(e1 * 0.70710678118654752f));
                }
                if (OUTM == OUT_F32) {
                    *reinterpret_cast<float2*>(C + off) = make_float2(e0, e1);
                } else {
                    __nv_bfloat162 hh2, ll2;
                    bsplit(e0, hh2.x, ll2.x);
                    bsplit(e1, hh2.y, ll2.y);
                    *reinterpret_cast<__nv_bfloat162*>(Chi + off) = hh2;
                    *reinterpret_cast<__nv_bfloat162*>(Clo + off) = ll2;
                }
            }
        }
    }
}

// ---------------------------------------------------------------------------
// Flash attention, fp32; epilogue emits bf16 hi/lo for the out-proj GEMM.
// ---------------------------------------------------------------------------
struct AttSmem {
    float Qs [64][65];
    float KVs[64][65];
    float Ps [64][65];
    float red[64][16];
    float m_run[64];
    float l_run[64];
    float alpha[64];
    float m_cur[64];
};

__global__ void __launch_bounds__(256) attn_kernel(
    const float* __restrict__ qx, const float* __restrict__ kv,
    __nv_bfloat16* __restrict__ out_h, __nv_bfloat16* __restrict__ out_l)
{
    extern __shared__ unsigned char smem_raw[];
    AttSmem& sm = *reinterpret_cast<AttSmem*>(smem_raw);

    const int t  = threadIdx.x;
    const int tx = t & 15, ty = t >> 4;
    const int r0 = ty * 4, c0 = tx * 4;
    const int qb = blockIdx.x * 64;
    const int h  = blockIdx.y;
    const int b  = blockIdx.z;

    const float* qptr = qx + ((size_t)b * SEQ) * C_DIM  + (size_t)h * DH;
    const float* kptr = kv + ((size_t)b * SEQ) * KV_DIM + (size_t)h * DH;
    const float* vptr = kptr + C_DIM;

    #pragma unroll
    for (int i = 0; i < 4; i++) {
        int vi = t + i * 256;
        int r  = vi >> 4;
        int d  = (vi & 15) * 4;
        float4 q4 = *reinterpret_cast<const float4*>(qptr + (size_t)(qb + r) * C_DIM + d);
        sm.Qs[r][d + 0] = q4.x; sm.Qs[r][d + 1] = q4.y;
        sm.Qs[r][d + 2] = q4.z; sm.Qs[r][d + 3] = q4.w;
    }
    if (t < 64) { sm.m_run[t] = -INFINITY; sm.l_run[t] = 0.f; }

    float o[4][4] = {};
    __syncthreads();

    for (int kt = 0; kt < 16; ++kt) {
        const int kb = kt * 64;

        #pragma unroll
        for (int i = 0; i < 4; i++) {
            int vi = t + i * 256;
            int r  = vi >> 4;
            int d  = (vi & 15) * 4;
            float4 k4 = *reinterpret_cast<const float4*>(kptr + (size_t)(kb + r) * KV_DIM + d);
            sm.KVs[r][d + 0] = k4.x; sm.KVs[r][d + 1] = k4.y;
            sm.KVs[r][d + 2] = k4.z; sm.KVs[r][d + 3] = k4.w;
        }
        __syncthreads();

        float s[4][4] = {};
        #pragma unroll 4
        for (int d = 0; d < 64; ++d) {
            float qf[4], kf[4];
            #pragma unroll
            for (int i = 0; i < 4; i++) qf[i] = sm.Qs[r0 + i][d];
            #pragma unroll
            for (int j = 0; j < 4; j++) kf[j] = sm.KVs[c0 + j][d];
            #pragma unroll
            for (int i = 0; i < 4; i++)
                #pragma unroll
                for (int j = 0; j < 4; j++) s[i][j] += qf[i] * kf[j];
        }
        #pragma unroll
        for (int i = 0; i < 4; i++)
            #pragma unroll
            for (int j = 0; j < 4; j++) s[i][j] *= 0.125f;

        __syncthreads();

        #pragma unroll
        for (int i = 0; i < 4; i++) {
            float mx = fmaxf(fmaxf(s[i][0], s[i][1]), fmaxf(s[i][2], s[i][3]));
            sm.red[r0 + i][tx] = mx;
        }
        __syncthreads();

        if (t < 64) {
            float mx = sm.red[t][0];
            #pragma unroll
            for (int jj = 1; jj < 16; jj++) mx = fmaxf(mx, sm.red[t][jj]);
            float mo = sm.m_run[t];
            float mn = fmaxf(mo, mx);
            sm.m_cur[t]  = mn;
            sm.alpha[t]  = expf(mo - mn);
            sm.m_run[t]  = mn;
        }
        __syncthreads();

        #pragma unroll
        for (int i = 0; i < 4; i++) {
            float mn = sm.m_cur[r0 + i];
            float ps = 0.f;
            #pragma unroll
            for (int j = 0; j < 4; j++) {
                float p = expf(s[i][j] - mn);
                sm.Ps[r0 + i][c0 + j] = p;
                ps += p;
            }
            sm.red[r0 + i][tx] = ps;
        }
        #pragma unroll
        for (int i = 0; i < 4; i++) {
            int vi = t + i * 256;
            int r  = vi >> 4;
            int d  = (vi & 15) * 4;
            float4 v4 = *reinterpret_cast<const float4*>(vptr + (size_t)(kb + r) * KV_DIM + d);
            sm.KVs[r][d + 0] = v4.x; sm.KVs[r][d + 1] = v4.y;
            sm.KVs[r][d + 2] = v4.z; sm.KVs[r][d + 3] = v4.w;
        }
        __syncthreads();

        if (t < 64) {
            float su = 0.f;
            #pragma unroll
            for (int jj = 0; jj < 16; jj++) su += sm.red[t][jj];
            sm.l_run[t] = sm.alpha[t] * sm.l_run[t] + su;
        }

        #pragma unroll
        for (int i = 0; i < 4; i++) {
            float a = sm.alpha[r0 + i];
            #pragma unroll
            for (int j = 0; j < 4; j++) o[i][j] *= a;
        }
        #pragma unroll 4
        for (int kk = 0; kk < 64; ++kk) {
            float pf[4], vf[4];
            #pragma unroll
            for (int i = 0; i < 4; i++) pf[i] = sm.Ps[r0 + i][kk];
            #pragma unroll
            for (int j = 0; j < 4; j++) vf[j] = sm.KVs[kk][c0 + j];
            #pragma unroll
            for (int i = 0; i < 4; i++)
                #pragma unroll
                for (int j = 0; j < 4; j++) o[i][j] += pf[i] * vf[j];
        }
        __syncthreads();
    }

    #pragma unroll
    for (int i = 0; i < 4; i++) {
        float inv = 1.0f / sm.l_run[r0 + i];
        const size_t off = ((size_t)b * SEQ + qb + r0 + i) * C_DIM + h * DH + c0;
        __nv_bfloat162 h01, h23, l01, l23;
        bsplit(o[i][0] * inv, h01.x, l01.x);
        bsplit(o[i][1] * inv, h01.y, l01.y);
        bsplit(o[i][2] * inv, h23.x, l23.x);
        bsplit(o[i][3] * inv, h23.y, l23.y);
        *reinterpret_cast<__nv_bfloat162*>(out_h + off)     = h01;
        *reinterpret_cast<__nv_bfloat162*>(out_h + off + 2) = h23;
        *reinterpret_cast<__nv_bfloat162*>(out_l + off)     = l01;
        *reinterpret_cast<__nv_bfloat162*>(out_l + off + 2) = l23;
    }
}

// ---------------------------------------------------------------------------
// Launch
// ---------------------------------------------------------------------------
extern "C" void kernel_launch(void* const* d_in, const int* in_sizes, int n_in,
                              void* d_out, int out_size)
{
    const float* x       = (const float*)d_in[0];
    const float* q_extra = (const float*)d_in[1];
    const float* ln1_g   = (const float*)d_in[2];
    const float* ln1_b   = (const float*)d_in[3];
    const float* w_kv    = (const float*)d_in[4];
    const float* w_out   = (const float*)d_in[5];
    const float* b_out   = (const float*)d_in[6];
    const float* ln2_g   = (const float*)d_in[7];
    const float* ln2_b   = (const float*)d_in[8];
    const float* w1      = (const float*)d_in[9];
    const float* b1      = (const float*)d_in[10];
    const float* w2      = (const float*)d_in[11];
    const float* b2      = (const float*)d_in[12];
    float* out = (float*)d_out;

    __nv_bfloat16 *xn_h, *xn_l, *att_h, *att_l, *h_h, *h_l, *hh_h, *hh_l;
    __nv_bfloat16 *wkv_h, *wkv_l, *wout_h, *wout_l, *w1_h, *w1_l, *w2_h, *w2_l;
    float *kvp, *x2;
    cudaGetSymbolAddress((void**)&xn_h,  g_xn_h);  cudaGetSymbolAddress((void**)&xn_l,  g_xn_l);
    cudaGetSymbolAddress((void**)&att_h, g_att_h); cudaGetSymbolAddress((void**)&att_l, g_att_l);
    cudaGetSymbolAddress((void**)&h_h,   g_h_h);   cudaGetSymbolAddress((void**)&h_l,   g_h_l);
    cudaGetSymbolAddress((void**)&hh_h,  g_hh_h);  cudaGetSymbolAddress((void**)&hh_l,  g_hh_l);
    cudaGetSymbolAddress((void**)&wkv_h, g_wkv_h); cudaGetSymbolAddress((void**)&wkv_l, g_wkv_l);
    cudaGetSymbolAddress((void**)&wout_h,g_wout_h);cudaGetSymbolAddress((void**)&wout_l,g_wout_l);
    cudaGetSymbolAddress((void**)&w1_h,  g_w1_h);  cudaGetSymbolAddress((void**)&w1_l,  g_w1_l);
    cudaGetSymbolAddress((void**)&w2_h,  g_w2_h);  cudaGetSymbolAddress((void**)&w2_l,  g_w2_l);
    cudaGetSymbolAddress((void**)&kvp,   g_kv);
    cudaGetSymbolAddress((void**)&x2,    g_x2);

    cudaFuncSetAttribute(attn_kernel, cudaFuncAttributeMaxDynamicSharedMemorySize,
                         (int)sizeof(AttSmem));
    cudaFuncSetAttribute(tgemm_bf3<EPI_NONE, OUT_F32>,
                         cudaFuncAttributeMaxDynamicSharedMemorySize, TG_SMEM);
    cudaFuncSetAttribute(tgemm_bf3<EPI_BIAS_RES, OUT_F32>,
                         cudaFuncAttributeMaxDynamicSharedMemorySize, TG_SMEM);
    cudaFuncSetAttribute(tgemm_bf3<EPI_BIAS_GELU, OUT_BF16>,
                         cudaFuncAttributeMaxDynamicSharedMemorySize, TG_SMEM);

    // 0) Weight transpose + bf16 split: [K,N] -> [N,K] hi/lo
    wsplit_t<<<dim3(KV_DIM / 32, C_DIM / 32), dim3(32, 8)>>>(w_kv,  wkv_h,  wkv_l,  C_DIM, KV_DIM);
    wsplit_t<<<dim3(C_DIM / 32,  C_DIM / 32), dim3(32, 8)>>>(w_out, wout_h, wout_l, C_DIM, C_DIM);
    wsplit_t<<<dim3(HID / 32,    C_DIM / 32), dim3(32, 8)>>>(w1,    w1_h,   w1_l,   C_DIM, HID);
    wsplit_t<<<dim3(C_DIM / 32,  HID / 32),   dim3(32, 8)>>>(w2,    w2_h,   w2_l,   HID,   C_DIM);

    // 1) xn = LN1(x)  (bf16 hi/lo)
    ln_kernel<<<TOKENS, 256>>>(x, ln1_g, ln1_b, xn_h, xn_l);

    // 2) kv = xn @ w_kv            [8192 x 1536, K=768]
    tgemm_bf3<EPI_NONE, OUT_F32><<<dim3(KV_DIM / 128, TOKENS / 128), 256, TG_SMEM>>>(
        TOKENS, KV_DIM, C_DIM, xn_h, xn_l, wkv_h, wkv_l,
        nullptr, nullptr, kvp, nullptr, nullptr);

    // 3) att = softmax(q k^T / 8) v   (bf16 hi/lo)
    attn_kernel<<<dim3(SEQ / 64, HEADS, BATCH), 256, sizeof(AttSmem)>>>(
        q_extra, kvp, att_h, att_l);

    // 4) x2 = x + att @ w_out + b_out   [8192 x 768, K=768]
    tgemm_bf3<EPI_BIAS_RES, OUT_F32><<<dim3(C_DIM / 128, TOKENS / 128), 256, TG_SMEM>>>(
        TOKENS, C_DIM, C_DIM, att_h, att_l, wout_h, wout_l,
        b_out, x, x2, nullptr, nullptr);

    // 5) h = LN2(x2)   (bf16 hi/lo)
    ln_kernel<<<TOKENS, 256>>>(x2, ln2_g, ln2_b, h_h, h_l);

    // 6) hh = gelu(h @ w1 + b1)   [8192 x 3072, K=768] (bf16 hi/lo)
    tgemm_bf3<EPI_BIAS_GELU, OUT_BF16><<<dim3(HID / 128, TOKENS / 128), 256, TG_SMEM>>>(
        TOKENS, HID, C_DIM, h_h, h_l, w1_h, w1_l,
        b1, nullptr, nullptr, hh_h, hh_l);

    // 7) out = x2 + hh @ w2 + b2   [8192 x 768, K=3072]
    tgemm_bf3<EPI_BIAS_RES, OUT_F32><<<dim3(C_DIM / 128, TOKENS / 128), 256, TG_SMEM>>>(
        TOKENS, C_DIM, HID, hh_h, hh_l, w2_h, w2_l,
        b2, x2, out, nullptr, nullptr);
}

// round 14
// speedup vs baseline: 1.5737x; 1.5737x over previous
#include <cuda_runtime.h>
#include <cuda_bf16.h>
#include <cuda_fp16.h>
#include <math.h>
#include <stdint.h>

// Problem constants
#define TOKENS 8192      // B*N = 8*1024
#define BATCH  8
#define SEQ    1024
#define C_DIM  768
#define KV_DIM 1536
#define HID    3072
#define HEADS  12
#define DH     64

// ---------------------------------------------------------------------------
// Scratch (device globals; no runtime allocation)
// ---------------------------------------------------------------------------
__device__ __nv_bfloat16 g_xn_h [TOKENS * C_DIM];
__device__ __nv_bfloat16 g_xn_l [TOKENS * C_DIM];
__device__ float         g_kv   [TOKENS * KV_DIM];
__device__ __nv_bfloat16 g_att_h[TOKENS * C_DIM];
__device__ __nv_bfloat16 g_att_l[TOKENS * C_DIM];
__device__ float         g_x2   [TOKENS * C_DIM];
__device__ __nv_bfloat16 g_h_h  [TOKENS * C_DIM];
__device__ __nv_bfloat16 g_h_l  [TOKENS * C_DIM];
__device__ __nv_bfloat16 g_hh_h [TOKENS * HID];
__device__ __nv_bfloat16 g_hh_l [TOKENS * HID];

// Transposed + bf16-split weights: [N, K] row-major (i.e. W^T)
__device__ __nv_bfloat16 g_wkv_h [KV_DIM * C_DIM];
__device__ __nv_bfloat16 g_wkv_l [KV_DIM * C_DIM];
__device__ __nv_bfloat16 g_wout_h[C_DIM * C_DIM];
__device__ __nv_bfloat16 g_wout_l[C_DIM * C_DIM];
__device__ __nv_bfloat16 g_w1_h  [HID * C_DIM];
__device__ __nv_bfloat16 g_w1_l  [HID * C_DIM];
__device__ __nv_bfloat16 g_w2_h  [C_DIM * HID];
__device__ __nv_bfloat16 g_w2_l  [C_DIM * HID];

// ---------------------------------------------------------------------------
// Helpers
// ---------------------------------------------------------------------------
__device__ __forceinline__ void bsplit(float v, __nv_bfloat16& h, __nv_bfloat16& l) {
    h = __float2bfloat16(v);
    l = __float2bfloat16(v - __bfloat162float(h));
}

// bf16 m16n8k16 MMA (row.col), fp32 accumulate
__device__ __forceinline__ void mma_bf16(float* c, const uint32_t* a,
                                         uint32_t b0, uint32_t b1) {
    asm volatile(
        "mma.sync.aligned.m16n8k16.row.col.f32.bf16.bf16.f32 "
        "{%0,%1,%2,%3}, {%4,%5,%6,%7}, {%8,%9}, {%0,%1,%2,%3};"
        : "+f"(c[0]), "+f"(c[1]), "+f"(c[2]), "+f"(c[3])
        : "r"(a[0]), "r"(a[1]), "r"(a[2]), "r"(a[3]), "r"(b0), "r"(b1));
}

// f16 m16n8k16 MMA (row.col), fp32 accumulate
__device__ __forceinline__ void mma_f16(float* c, const uint32_t* a,
                                        uint32_t b0, uint32_t b1) {
    asm volatile(
        "mma.sync.aligned.m16n8k16.row.col.f32.f16.f16.f32 "
        "{%0,%1,%2,%3}, {%4,%5,%6,%7}, {%8,%9}, {%0,%1,%2,%3};"
        : "+f"(c[0]), "+f"(c[1]), "+f"(c[2]), "+f"(c[3])
        : "r"(a[0]), "r"(a[1]), "r"(a[2]), "r"(a[3]), "r"(b0), "r"(b1));
}

#define CP_ASYNC16(smem_u32, gptr) \
    asm volatile("cp.async.cg.shared.global [%0], [%1], 16;" \
        :: "r"(smem_u32), "l"(gptr) : "memory")
#define CP_COMMIT() asm volatile("cp.async.commit_group;" ::: "memory")
#define CP_WAIT1()  asm volatile("cp.async.wait_group 1;" ::: "memory")
#define CP_WAIT0()  asm volatile("cp.async.wait_group 0;" ::: "memory")

// ---------------------------------------------------------------------------
// Weight transpose + bf16 split: w[K,N] fp32 -> th/tl[N,K] bf16
// ---------------------------------------------------------------------------
__global__ void __launch_bounds__(256) wsplit_t(
    const float* __restrict__ w, __nv_bfloat16* __restrict__ th,
    __nv_bfloat16* __restrict__ tl, int K, int N)
{
    __shared__ float tile[32][33];
    const int n0 = blockIdx.x * 32, k0 = blockIdx.y * 32;
    const int tx = threadIdx.x, ty = threadIdx.y;
    #pragma unroll
    for (int i = ty; i < 32; i += 8)
        tile[i][tx] = w[(size_t)(k0 + i) * N + n0 + tx];
    __syncthreads();
    #pragma unroll
    for (int i = ty; i < 32; i += 8) {
        float v = tile[tx][i];                 // = w[k0+tx][n0+i]
        __nv_bfloat16 h, l; bsplit(v, h, l);
        size_t o = (size_t)(n0 + i) * K + k0 + tx;
        th[o] = h; tl[o] = l;
    }
}

// ---------------------------------------------------------------------------
// LayerNorm -> bf16 hi/lo outputs
// ---------------------------------------------------------------------------
__global__ void __launch_bounds__(256) ln_kernel(
    const float* __restrict__ x, const float* __restrict__ g,
    const float* __restrict__ b,
    __nv_bfloat16* __restrict__ hi, __nv_bfloat16* __restrict__ lo)
{
    __shared__ float sh[9];
    const int row = blockIdx.x;
    const int t = threadIdx.x;
    const float* xr = x + (size_t)row * C_DIM;

    float v0 = xr[t], v1 = xr[t + 256], v2 = xr[t + 512];

    float s = v0 + v1 + v2;
    #pragma unroll
    for (int o = 16; o; o >>= 1) s += __shfl_xor_sync(0xffffffffu, s, o);
    if ((t & 31) == 0) sh[t >> 5] = s;
    __syncthreads();
    if (t == 0) {
        float a = 0.f;
        #pragma unroll
        for (int i = 0; i < 8; i++) a += sh[i];
        sh[8] = a * (1.0f / C_DIM);
    }
    __syncthreads();
    const float mu = sh[8];

    float d0 = v0 - mu, d1 = v1 - mu, d2 = v2 - mu;
    float q = d0 * d0 + d1 * d1 + d2 * d2;
    __syncthreads();
    #pragma unroll
    for (int o = 16; o; o >>= 1) q += __shfl_xor_sync(0xffffffffu, q, o);
    if ((t & 31) == 0) sh[t >> 5] = q;
    __syncthreads();
    if (t == 0) {
        float a = 0.f;
        #pragma unroll
        for (int i = 0; i < 8; i++) a += sh[i];
        sh[8] = rsqrtf(a * (1.0f / C_DIM) + 1e-5f);
    }
    __syncthreads();
    const float rs = sh[8];

    const size_t rb = (size_t)row * C_DIM;
    float vals[3] = { d0 * rs * g[t] + b[t],
                      d1 * rs * g[t + 256] + b[t + 256],
                      d2 * rs * g[t + 512] + b[t + 512] };
    #pragma unroll
    for (int i = 0; i < 3; i++) {
        __nv_bfloat16 h, l; bsplit(vals[i], h, l);
        hi[rb + t + i * 256] = h;
        lo[rb + t + i * 256] = l;
    }
}

// ---------------------------------------------------------------------------
// bf16x3 tensor-core GEMM (unchanged, validated in R13)
// ---------------------------------------------------------------------------
enum { EPI_NONE = 0, EPI_BIAS_RES = 1, EPI_BIAS_GELU = 2 };
enum { OUT_F32 = 0, OUT_BF16 = 1 };

#define BK 32
#define ST 40
#define ARR_ELEMS (128 * ST)
#define STAGE_ELEMS (4 * ARR_ELEMS)
#define TG_SMEM (2 * STAGE_ELEMS * 2)

template <int EPI, int OUTM>
__global__ void __launch_bounds__(256) tgemm_bf3(
    int M, int N, int K,
    const __nv_bfloat16* __restrict__ Ahi, const __nv_bfloat16* __restrict__ Alo,
    const __nv_bfloat16* __restrict__ Bth, const __nv_bfloat16* __restrict__ Btl,
    const float* __restrict__ bias, const float* __restrict__ resid,
    float* __restrict__ C,
    __nv_bfloat16* __restrict__ Chi, __nv_bfloat16* __restrict__ Clo)
{
    extern __shared__ __nv_bfloat16 smem[];
    const uint32_t smb = (uint32_t)__cvta_generic_to_shared(smem);

    const int t    = threadIdx.x;
    const int lane = t & 31;
    const int warp = t >> 5;
    const int wm   = (warp >> 2) * 64;
    const int wn   = (warp & 3) * 32;
    const int g    = lane >> 2;
    const int ti   = lane & 3;

    const __nv_bfloat16* Ab_h = Ahi + (size_t)blockIdx.y * 128 * K;
    const __nv_bfloat16* Ab_l = Alo + (size_t)blockIdx.y * 128 * K;
    const __nv_bfloat16* Bb_h = Bth + (size_t)blockIdx.x * 128 * K;
    const __nv_bfloat16* Bb_l = Btl + (size_t)blockIdx.x * 128 * K;
    const __nv_bfloat16* srcs[4] = { Ab_h, Ab_l, Bb_h, Bb_l };

    const int r0l = (t) >> 2,        q0l = (t) & 3;
    const int r1l = (t + 256) >> 2,  q1l = (t + 256) & 3;

    auto issue = [&](int c) {
        const int s = c & 1;
        const uint32_t sb = smb + s * (STAGE_ELEMS * 2);
        #pragma unroll
        for (int arr = 0; arr < 4; ++arr) {
            const __nv_bfloat16* src = srcs[arr] + c * BK;
            const uint32_t db = sb + arr * (ARR_ELEMS * 2);
            CP_ASYNC16(db + (uint32_t)(r0l * (ST * 2) + q0l * 16),
                       src + (size_t)r0l * K + q0l * 8);
            CP_ASYNC16(db + (uint32_t)(r1l * (ST * 2) + q1l * 16),
                       src + (size_t)r1l * K + q1l * 8);
        }
        CP_COMMIT();
    };

    float acc[4][4][4];
    #pragma unroll
    for (int i = 0; i < 4; i++)
        #pragma unroll
        for (int j = 0; j < 4; j++)
            #pragma unroll
            for (int k = 0; k < 4; k++) acc[i][j][k] = 0.f;

    const int nStages = K / BK;
    issue(0);
    if (nStages > 1) issue(1);

    for (int c = 0; c < nStages; ++c) {
        if (c + 1 < nStages) { CP_WAIT1(); } else { CP_WAIT0(); }
        __syncthreads();

        const int s = c & 1;
        const __nv_bfloat16* sAh = smem + s * STAGE_ELEMS;
        const __nv_bfloat16* sAl = sAh + ARR_ELEMS;
        const __nv_bfloat16* sBh = sAl + ARR_ELEMS;
        const __nv_bfloat16* sBl = sBh + ARR_ELEMS;

        #pragma unroll
        for (int ks = 0; ks < BK; ks += 16) {
            uint32_t ah[4][4], al[4][4];
            #pragma unroll
            for (int ib = 0; ib < 4; ++ib) {
                const int rb = (wm + ib * 16 + g) * ST + ks + 2 * ti;
                ah[ib][0] = *reinterpret_cast<const uint32_t*>(sAh + rb);
                ah[ib][1] = *reinterpret_cast<const uint32_t*>(sAh + rb + 8 * ST);
                ah[ib][2] = *reinterpret_cast<const uint32_t*>(sAh + rb + 8);
                ah[ib][3] = *reinterpret_cast<const uint32_t*>(sAh + rb + 8 * ST + 8);
                al[ib][0] = *reinterpret_cast<const uint32_t*>(sAl + rb);
                al[ib][1] = *reinterpret_cast<const uint32_t*>(sAl + rb + 8 * ST);
                al[ib][2] = *reinterpret_cast<const uint32_t*>(sAl + rb + 8);
                al[ib][3] = *reinterpret_cast<const uint32_t*>(sAl + rb + 8 * ST + 8);
            }
            #pragma unroll
            for (int jb = 0; jb < 4; ++jb) {
                const int nb = (wn + jb * 8 + g) * ST + ks + 2 * ti;
                const uint32_t bh0 = *reinterpret_cast<const uint32_t*>(sBh + nb);
                const uint32_t bh1 = *reinterpret_cast<const uint32_t*>(sBh + nb + 8);
                const uint32_t bl0 = *reinterpret_cast<const uint32_t*>(sBl + nb);
                const uint32_t bl1 = *reinterpret_cast<const uint32_t*>(sBl + nb + 8);
                #pragma unroll
                for (int ib = 0; ib < 4; ++ib) {
                    mma_bf16(acc[ib][jb], ah[ib], bh0, bh1);
                    mma_bf16(acc[ib][jb], ah[ib], bl0, bl1);
                    mma_bf16(acc[ib][jb], al[ib], bh0, bh1);
                }
            }
        }
        __syncthreads();
        if (c + 2 < nStages) issue(c + 2);
    }

    const int row0 = blockIdx.y * 128 + wm;
    const int col0 = blockIdx.x * 128 + wn;
    #pragma unroll
    for (int ib = 0; ib < 4; ++ib) {
        #pragma unroll
        for (int jb = 0; jb < 4; ++jb) {
            const int cc = col0 + jb * 8 + 2 * ti;
            #pragma unroll
            for (int half = 0; half < 2; half++) {
                const int r = row0 + ib * 16 + g + half * 8;
                float e0 = acc[ib][jb][half * 2 + 0];
                float e1 = acc[ib][jb][half * 2 + 1];
                const size_t off = (size_t)r * N + cc;
                if (EPI != EPI_NONE) {
                    e0 += bias[cc];
                    e1 += bias[cc + 1];
                }
                if (EPI == EPI_BIAS_RES) {
                    float2 rr = *reinterpret_cast<const float2*>(resid + off);
                    e0 += rr.x;
                    e1 += rr.y;
                }
                if (EPI == EPI_BIAS_GELU) {
                    e0 = 0.5f * e0 * (1.0f + erff(e0 * 0.70710678118654752f));
                    e1 = 0.5f * e1 * (1.0f + erff(e1 * 0.70710678118654752f));
                }
                if (OUTM == OUT_F32) {
                    *reinterpret_cast<float2*>(C + off) = make_float2(e0, e1);
                } else {
                    __nv_bfloat162 hh2, ll2;
                    bsplit(e0, hh2.x, ll2.x);
                    bsplit(e1, hh2.y, ll2.y);
                    *reinterpret_cast<__nv_bfloat162*>(Chi + off) = hh2;
                    *reinterpret_cast<__nv_bfloat162*>(Clo + off) = ll2;
                }
            }
        }
    }
}

// ---------------------------------------------------------------------------
// Tensor-core flash attention (f16 MMA).
// Block: 128 Q rows x one (batch, head). 256 threads = 8 warps, warp owns 16 rows.
// QK^T: Q (x0.125) split hi/lo f16 x K single f16 (2 MMAs).
// PV:   P f16 (from expf) x V f16 (1 MMA). fp32 accumulators, online softmax.
// Smem strides: 72 halves (conflict-free fragment access, validated pattern).
// ---------------------------------------------------------------------------
#define AST2 72
#define ATT_SMEM ((2 * 128 * AST2 + 2 * 64 * AST2) * 2)   // 55296 bytes

__global__ void __launch_bounds__(256) attn_tc(
    const float* __restrict__ qx, const float* __restrict__ kv,
    __nv_bfloat16* __restrict__ out_h, __nv_bfloat16* __restrict__ out_l)
{
    extern __shared__ __half asm_[];
    __half* Qh = asm_;
    __half* Ql = Qh + 128 * AST2;
    __half* Ks = Ql + 128 * AST2;
    __half* Vs = Ks + 64 * AST2;

    const int t    = threadIdx.x;
    const int lane = t & 31;
    const int warp = t >> 5;
    const int g    = lane >> 2;
    const int ti   = lane & 3;

    const int qb = blockIdx.x * 128;
    const int h  = blockIdx.y;
    const int b  = blockIdx.z;

    const float* qptr = qx + ((size_t)b * SEQ) * C_DIM  + (size_t)h * DH;
    const float* kptr = kv + ((size_t)b * SEQ) * KV_DIM + (size_t)h * DH;
    const float* vptr = kptr + C_DIM;

    // Load Q tile (128x64), scale by 1/8, split f16 hi/lo
    #pragma unroll
    for (int i = 0; i < 8; i++) {
        int idx = t + i * 256;           // 0..2047 float4s
        int r   = idx >> 4;
        int c4  = (idx & 15) * 4;
        float4 q4 = *reinterpret_cast<const float4*>(qptr + (size_t)(qb + r) * C_DIM + c4);
        float v[4] = { q4.x * 0.125f, q4.y * 0.125f, q4.z * 0.125f, q4.w * 0.125f };
        __half hh[4], ll[4];
        #pragma unroll
        for (int j = 0; j < 4; j++) {
            hh[j] = __float2half_rn(v[j]);
            ll[j] = __float2half_rn(v[j] - __half2float(hh[j]));
        }
        __half2 h01 = __halves2half2(hh[0], hh[1]), h23 = __halves2half2(hh[2], hh[3]);
        __half2 l01 = __halves2half2(ll[0], ll[1]), l23 = __halves2half2(ll[2], ll[3]);
        uint2 hu = make_uint2(*reinterpret_cast<uint32_t*>(&h01), *reinterpret_cast<uint32_t*>(&h23));
        uint2 lu = make_uint2(*reinterpret_cast<uint32_t*>(&l01), *reinterpret_cast<uint32_t*>(&l23));
        *reinterpret_cast<uint2*>(Qh + r * AST2 + c4) = hu;
        *reinterpret_cast<uint2*>(Ql + r * AST2 + c4) = lu;
    }

    float m0 = -INFINITY, m1 = -INFINITY, l0 = 0.f, l1 = 0.f;
    float acc[8][4];
    #pragma unroll
    for (int nb = 0; nb < 8; nb++)
        #pragma unroll
        for (int k = 0; k < 4; k++) acc[nb][k] = 0.f;

    __syncthreads();

    const uint32_t* Qh32 = reinterpret_cast<const uint32_t*>(Qh);
    const uint32_t* Ql32 = reinterpret_cast<const uint32_t*>(Ql);
    const uint32_t* Ks32 = reinterpret_cast<const uint32_t*>(Ks);

    for (int kt = 0; kt < 16; ++kt) {
        const int kb = kt * 64;

        // Load K and V tiles (64x64 each), convert f16
        #pragma unroll
        for (int i = 0; i < 4; i++) {
            int idx = t + i * 256;        // 0..1023 float4s
            int r   = idx >> 4;
            int c4  = (idx & 15) * 4;
            float4 k4 = *reinterpret_cast<const float4*>(kptr + (size_t)(kb + r) * KV_DIM + c4);
            float4 v4 = *reinterpret_cast<const float4*>(vptr + (size_t)(kb + r) * KV_DIM + c4);
            __half2 ka = __floats2half2_rn(k4.x, k4.y), kb2 = __floats2half2_rn(k4.z, k4.w);
            __half2 va = __floats2half2_rn(v4.x, v4.y), vb2 = __floats2half2_rn(v4.z, v4.w);
            *reinterpret_cast<uint2*>(Ks + r * AST2 + c4) =
                make_uint2(*reinterpret_cast<uint32_t*>(&ka), *reinterpret_cast<uint32_t*>(&kb2));
            *reinterpret_cast<uint2*>(Vs + r * AST2 + c4) =
                make_uint2(*reinterpret_cast<uint32_t*>(&va), *reinterpret_cast<uint32_t*>(&vb2));
        }
        __syncthreads();

        // S = (Q*0.125) @ K^T  via 2 MMAs (Qh + Ql)
        float s[8][4];
        #pragma unroll
        for (int nb = 0; nb < 8; nb++)
            #pragma unroll
            for (int k = 0; k < 4; k++) s[nb][k] = 0.f;

        #pragma unroll
        for (int kbk = 0; kbk < 4; ++kbk) {
            const int abase = (warp * 16 + g) * (AST2 / 2) + kbk * 8 + ti;
            uint32_t ah[4], al[4];
            ah[0] = Qh32[abase];
            ah[1] = Qh32[abase + 8 * (AST2 / 2)];
            ah[2] = Qh32[abase + 4];
            ah[3] = Qh32[abase + 8 * (AST2 / 2) + 4];
            al[0] = Ql32[abase];
            al[1] = Ql32[abase + 8 * (AST2 / 2)];
            al[2] = Ql32[abase + 4];
            al[3] = Ql32[abase + 8 * (AST2 / 2) + 4];
            #pragma unroll
            for (int nb = 0; nb < 8; ++nb) {
                const int bbase = (nb * 8 + g) * (AST2 / 2) + kbk * 8 + ti;
                const uint32_t b0 = Ks32[bbase];
                const uint32_t b1 = Ks32[bbase + 4];
                mma_f16(s[nb], ah, b0, b1);
                mma_f16(s[nb], al, b0, b1);
            }
        }

        // Online softmax (rows g and g+8, warp-private; quad reduce)
        float mx0 = -INFINITY, mx1 = -INFINITY;
        #pragma unroll
        for (int nb = 0; nb < 8; nb++) {
            mx0 = fmaxf(mx0, fmaxf(s[nb][0], s[nb][1]));
            mx1 = fmaxf(mx1, fmaxf(s[nb][2], s[nb][3]));
        }
        mx0 = fmaxf(mx0, __shfl_xor_sync(0xffffffffu, mx0, 1));
        mx0 = fmaxf(mx0, __shfl_xor_sync(0xffffffffu, mx0, 2));
        mx1 = fmaxf(mx1, __shfl_xor_sync(0xffffffffu, mx1, 1));
        mx1 = fmaxf(mx1, __shfl_xor_sync(0xffffffffu, mx1, 2));

        const float mn0 = fmaxf(m0, mx0), mn1 = fmaxf(m1, mx1);
        const float a0 = expf(m0 - mn0), a1 = expf(m1 - mn1);
        m0 = mn0; m1 = mn1;
        l0 *= a0; l1 *= a1;
        #pragma unroll
        for (int nb = 0; nb < 8; nb++) {
            acc[nb][0] *= a0; acc[nb][1] *= a0;
            acc[nb][2] *= a1; acc[nb][3] *= a1;
        }

        // P = exp(S - m), packed f16x2 = PV A-fragments
        uint32_t p01[8], p23[8];
        #pragma unroll
        for (int nb = 0; nb < 8; nb++) {
            float e0 = expf(s[nb][0] - m0);
            float e1 = expf(s[nb][1] - m0);
            float e2 = expf(s[nb][2] - m1);
            float e3 = expf(s[nb][3] - m1);
            l0 += e0 + e1; l1 += e2 + e3;
            __half2 q01 = __floats2half2_rn(e0, e1);
            __half2 q23 = __floats2half2_rn(e2, e3);
            p01[nb] = *reinterpret_cast<uint32_t*>(&q01);
            p23[nb] = *reinterpret_cast<uint32_t*>(&q23);
        }

        // O += P @ V  (V row-major [kv][dh]; b-frags via 2x LDS16 + pack)
        #pragma unroll
        for (int kbk = 0; kbk < 4; ++kbk) {
            uint32_t a[4] = { p01[2 * kbk], p23[2 * kbk], p01[2 * kbk + 1], p23[2 * kbk + 1] };
            #pragma unroll
            for (int nb = 0; nb < 8; ++nb) {
                const int n = nb * 8 + g;
                const int k0 = kbk * 16 + 2 * ti;
                const uint16_t* vp = reinterpret_cast<const uint16_t*>(Vs);
                uint32_t b0 = (uint32_t)vp[k0 * AST2 + n] |
                              ((uint32_t)vp[(k0 + 1) * AST2 + n] << 16);
                uint32_t b1 = (uint32_t)vp[(k0 + 8) * AST2 + n] |
                              ((uint32_t)vp[(k0 + 9) * AST2 + n] << 16);
                mma_f16(acc[nb], a, b0, b1);
            }
        }
        __syncthreads();
    }

    // Finalize: quad-reduce l, normalize, write bf16 hi/lo
    l0 += __shfl_xor_sync(0xffffffffu, l0, 1);
    l0 += __shfl_xor_sync(0xffffffffu, l0, 2);
    l1 += __shfl_xor_sync(0xffffffffu, l1, 1);
    l1 += __shfl_xor_sync(0xffffffffu, l1, 2);
    const float inv0 = 1.0f / l0, inv1 = 1.0f / l1;

    const size_t row0 = (size_t)b * SEQ + qb + warp * 16 + g;
    const size_t row1 = row0 + 8;
    #pragma unroll
    for (int nb = 0; nb < 8; nb++) {
        const int col = h * DH + nb * 8 + 2 * ti;
        __nv_bfloat162 h2, l2;
        bsplit(acc[nb][0] * inv0, h2.x, l2.x);
        bsplit(acc[nb][1] * inv0, h2.y, l2.y);
        *reinterpret_cast<__nv_bfloat162*>(out_h + row0 * C_DIM + col) = h2;
        *reinterpret_cast<__nv_bfloat162*>(out_l + row0 * C_DIM + col) = l2;
        bsplit(acc[nb][2] * inv1, h2.x, l2.x);
        bsplit(acc[nb][3] * inv1, h2.y, l2.y);
        *reinterpret_cast<__nv_bfloat162*>(out_h + row1 * C_DIM + col) = h2;
        *reinterpret_cast<__nv_bfloat162*>(out_l + row1 * C_DIM + col) = l2;
    }
}

// ---------------------------------------------------------------------------
// Launch
// ---------------------------------------------------------------------------
extern "C" void kernel_launch(void* const* d_in, const int* in_sizes, int n_in,
                              void* d_out, int out_size)
{
    const float* x       = (const float*)d_in[0];
    const float* q_extra = (const float*)d_in[1];
    const float* ln1_g   = (const float*)d_in[2];
    const float* ln1_b   = (const float*)d_in[3];
    const float* w_kv    = (const float*)d_in[4];
    const float* w_out   = (const float*)d_in[5];
    const float* b_out   = (const float*)d_in[6];
    const float* ln2_g   = (const float*)d_in[7];
    const float* ln2_b   = (const float*)d_in[8];
    const float* w1      = (const float*)d_in[9];
    const float* b1      = (const float*)d_in[10];
    const float* w2      = (const float*)d_in[11];
    const float* b2      = (const float*)d_in[12];
    float* out = (float*)d_out;

    __nv_bfloat16 *xn_h, *xn_l, *att_h, *att_l, *h_h, *h_l, *hh_h, *hh_l;
    __nv_bfloat16 *wkv_h, *wkv_l, *wout_h, *wout_l, *w1_h, *w1_l, *w2_h, *w2_l;
    float *kvp, *x2;
    cudaGetSymbolAddress((void**)&xn_h,  g_xn_h);  cudaGetSymbolAddress((void**)&xn_l,  g_xn_l);
    cudaGetSymbolAddress((void**)&att_h, g_att_h); cudaGetSymbolAddress((void**)&att_l, g_att_l);
    cudaGetSymbolAddress((void**)&h_h,   g_h_h);   cudaGetSymbolAddress((void**)&h_l,   g_h_l);
    cudaGetSymbolAddress((void**)&hh_h,  g_hh_h);  cudaGetSymbolAddress((void**)&hh_l,  g_hh_l);
    cudaGetSymbolAddress((void**)&wkv_h, g_wkv_h); cudaGetSymbolAddress((void**)&wkv_l, g_wkv_l);
    cudaGetSymbolAddress((void**)&wout_h,g_wout_h);cudaGetSymbolAddress((void**)&wout_l,g_wout_l);
    cudaGetSymbolAddress((void**)&w1_h,  g_w1_h);  cudaGetSymbolAddress((void**)&w1_l,  g_w1_l);
    cudaGetSymbolAddress((void**)&w2_h,  g_w2_h);  cudaGetSymbolAddress((void**)&w2_l,  g_w2_l);
    cudaGetSymbolAddress((void**)&kvp,   g_kv);
    cudaGetSymbolAddress((void**)&x2,    g_x2);

    cudaFuncSetAttribute(attn_tc, cudaFuncAttributeMaxDynamicSharedMemorySize, ATT_SMEM);
    cudaFuncSetAttribute(tgemm_bf3<EPI_NONE, OUT_F32>,
                         cudaFuncAttributeMaxDynamicSharedMemorySize, TG_SMEM);
    cudaFuncSetAttribute(tgemm_bf3<EPI_BIAS_RES, OUT_F32>,
                         cudaFuncAttributeMaxDynamicSharedMemorySize, TG_SMEM);
    cudaFuncSetAttribute(tgemm_bf3<EPI_BIAS_GELU, OUT_BF16>,
                         cudaFuncAttributeMaxDynamicSharedMemorySize, TG_SMEM);

    // 0) Weight transpose + bf16 split: [K,N] -> [N,K] hi/lo
    wsplit_t<<<dim3(KV_DIM / 32, C_DIM / 32), dim3(32, 8)>>>(w_kv,  wkv_h,  wkv_l,  C_DIM, KV_DIM);
    wsplit_t<<<dim3(C_DIM / 32,  C_DIM / 32), dim3(32, 8)>>>(w_out, wout_h, wout_l, C_DIM, C_DIM);
    wsplit_t<<<dim3(HID / 32,    C_DIM / 32), dim3(32, 8)>>>(w1,    w1_h,   w1_l,   C_DIM, HID);
    wsplit_t<<<dim3(C_DIM / 32,  HID / 32),   dim3(32, 8)>>>(w2,    w2_h,   w2_l,   HID,   C_DIM);

    // 1) xn = LN1(x)  (bf16 hi/lo)
    ln_kernel<<<TOKENS, 256>>>(x, ln1_g, ln1_b, xn_h, xn_l);

    // 2) kv = xn @ w_kv            [8192 x 1536, K=768]
    tgemm_bf3<EPI_NONE, OUT_F32><<<dim3(KV_DIM / 128, TOKENS / 128), 256, TG_SMEM>>>(
        TOKENS, KV_DIM, C_DIM, xn_h, xn_l, wkv_h, wkv_l,
        nullptr, nullptr, kvp, nullptr, nullptr);

    // 3) att = softmax(q k^T / 8) v   (tensor-core flash attention)
    attn_tc<<<dim3(SEQ / 128, HEADS, BATCH), 256, ATT_SMEM>>>(q_extra, kvp, att_h, att_l);

    // 4) x2 = x + att @ w_out + b_out   [8192 x 768, K=768]
    tgemm_bf3<EPI_BIAS_RES, OUT_F32><<<dim3(C_DIM / 128, TOKENS / 128), 256, TG_SMEM>>>(
        TOKENS, C_DIM, C_DIM, att_h, att_l, wout_h, wout_l,
        b_out, x, x2, nullptr, nullptr);

    // 5) h = LN2(x2)   (bf16 hi/lo)
    ln_kernel<<<TOKENS, 256>>>(x2, ln2_g, ln2_b, h_h, h_l);

    // 6) hh = gelu(h @ w1 + b1)   [8192 x 3072, K=768] (bf16 hi/lo)
    tgemm_bf3<EPI_BIAS_GELU, OUT_BF16><<<dim3(HID / 128, TOKENS / 128), 256, TG_SMEM>>>(
        TOKENS, HID, C_DIM, h_h, h_l, w1_h, w1_l,
        b1, nullptr, nullptr, hh_h, hh_l);

    // 7) out = x2 + hh @ w2 + b2   [8192 x 768, K=3072]
    tgemm_bf3<EPI_BIAS_RES, OUT_F32><<<dim3(C_DIM / 128, TOKENS / 128), 256, TG_SMEM>>>(
        TOKENS, C_DIM, HID, hh_h, hh_l, w2_h, w2_l,
        b2, x2, out, nullptr, nullptr);
}